// round 6
// baseline (speedup 1.0000x reference)
#include <cuda_runtime.h>
#include <cstdint>

#define DINL __device__ __forceinline__

constexpr int Tt = 96, Nn = 400, Fd = 256;
constexpr int Bb = 8;
constexpr int Mtot = Bb * Tt * Nn;              // 307200
constexpr int HEADS = Bb * Nn;                  // 3200
constexpr long BUF_ELEMS = (long)Mtot * Fd;     // 78,643,200

// ---------------- scratch (device globals; no allocation APIs) ----------------
__device__ float g_bufA[BUF_ELEMS];                 // q  -> ff1 out
__device__ float g_bufB[BUF_ELEMS];                 // k  -> ff2 out (pre-LN)
__device__ float g_bufC[BUF_ELEMS];                 // v  -> attn-proj out / out1
__device__ float g_bufY[BUF_ELEMS];                 // attention output [B,T,N,F]
__device__ float g_bufX[BUF_ELEMS];                 // tf32(xl + te)
__device__ float g_bufH[BUF_ELEMS];                 // tf32(xh + te)
__device__ float g_bufW[6 * 256 * 256];             // pre-packed tf32 weight fragments

DINL float* bufptr(int id) {
    switch (id) {
        case 0: return g_bufA;
        case 1: return g_bufB;
        case 2: return g_bufC;
        case 3: return g_bufY;
        case 5: return g_bufX;
        default: return g_bufH;
    }
}

// ---------------- tf32 + async-copy helpers ----------------
DINL uint32_t f2tf(float x) {
    uint32_t r;
    asm("cvt.rna.tf32.f32 %0, %1;" : "=r"(r) : "f"(x));
    return r;
}
DINL float tf2f(float x) { return __uint_as_float(f2tf(x)); }

DINL void mma8(float* c, const uint32_t* a, const uint32_t* b) {
    asm volatile(
        "mma.sync.aligned.m16n8k8.row.col.f32.tf32.tf32.f32 "
        "{%0,%1,%2,%3}, {%4,%5,%6,%7}, {%8,%9}, {%0,%1,%2,%3};"
        : "+f"(c[0]), "+f"(c[1]), "+f"(c[2]), "+f"(c[3])
        : "r"(a[0]), "r"(a[1]), "r"(a[2]), "r"(a[3]), "r"(b[0]), "r"(b[1]));
}

DINL void cpa16(float* smem_dst, const float* gsrc) {
    uint32_t d = (uint32_t)__cvta_generic_to_shared(smem_dst);
    asm volatile("cp.async.cg.shared.global [%0], [%1], 16;\n" :: "r"(d), "l"(gsrc));
}
#define CP_COMMIT()  asm volatile("cp.async.commit_group;\n")
#define CP_WAIT(n)   asm volatile("cp.async.wait_group %0;\n" :: "n"(n))

// =====================================================================
// Pre-pass: X = tf32(xl + te), H = tf32(xh + te)
// =====================================================================
__global__ __launch_bounds__(256) void prep_x(
    const float* __restrict__ xl, const float* __restrict__ xh,
    const float* __restrict__ te)
{
    long i = (long)blockIdx.x * 256 + threadIdx.x;   // float4 index
    long e = i * 4;
    int m = (int)(e >> 8);
    int bt = m / Nn;
    int f = (int)(e & 255);
    float4 t4 = *(const float4*)(te + bt * 256 + f);
    float4 a = *(const float4*)(xl + e);
    float4 b = *(const float4*)(xh + e);
    a.x = tf2f(a.x + t4.x); a.y = tf2f(a.y + t4.y);
    a.z = tf2f(a.z + t4.z); a.w = tf2f(a.w + t4.w);
    b.x = tf2f(b.x + t4.x); b.y = tf2f(b.y + t4.y);
    b.z = tf2f(b.z + t4.z); b.w = tf2f(b.w + t4.w);
    *(float4*)(g_bufX + e) = a;
    *(float4*)(g_bufH + e) = b;
}

// =====================================================================
// Pack all 6 weights [256x256] (W[n][k]) into fragment layout:
//   g_bufW[widx*65536 + ((kb*32 + nb)*32 + lane)*2 + reg]
//   kb = k>>3, nb = n>>3, lane = (n&7)*4 + (k&3), reg = (k>>2)&1
// A 32-wide k-tile (4 kb blocks) is a CONTIGUOUS 8192-float chunk.
// =====================================================================
__global__ __launch_bounds__(256) void pack_w6(
    const float* __restrict__ W0, const float* __restrict__ W1,
    const float* __restrict__ W2, const float* __restrict__ W3,
    const float* __restrict__ W4, const float* __restrict__ W5)
{
    int widx = blockIdx.x >> 8;
    const float* W;
    switch (widx) {
        case 0: W = W0; break;
        case 1: W = W1; break;
        case 2: W = W2; break;
        case 3: W = W3; break;
        case 4: W = W4; break;
        default: W = W5; break;
    }
    int i = (blockIdx.x & 255) * 256 + threadIdx.x;  // 0..65535
    int n = i >> 8, k = i & 255;
    int kb = k >> 3, nb = n >> 3;
    int lanei = (n & 7) * 4 + (k & 3);
    int reg = (k >> 2) & 1;
    g_bufW[widx * 65536 + ((kb * 32 + nb) * 32 + lanei) * 2 + reg] = tf2f(W[i]);
}

// =====================================================================
// Dense GEMM v4: out[m,n] = act( A[m,:] @ W[n,:] + bias[n] (+R) )
// M=307200, N=256, K=256. BM=128, BN=256, BK=32. 512 threads (4x4 warps).
// Double-buffered cp.async; zero cvt in mainloop.
// =====================================================================
constexpr int A_STRIDE = 36;                     // 32 + 4 pad
constexpr int A_TILE = 128 * A_STRIDE;           // 4608 floats per buffer
constexpr int B_TILE = 8192;                     // 32k x 256n packed slice
constexpr int GEMM_SMEM = (2 * B_TILE + 2 * A_TILE) * 4;   // 102400 bytes

__global__ __launch_bounds__(512, 1) void gemm_f(
    int a_id, const float* __restrict__ Wp, const float* __restrict__ bias,
    int r_id, float* __restrict__ Oext, int o_id,
    int relu, int trans, int rmode, int docvt)
{
    extern __shared__ float sm[];
    float* Bs = sm;                      // 2 x 8192
    float* As = sm + 2 * B_TILE;         // 2 x 4608

    const int tid = threadIdx.x;
    const int lane = tid & 31, wid = tid >> 5;   // 16 warps
    const int wm = wid & 3, wn = wid >> 2;       // 4 x 4
    const int m0 = blockIdx.x * 128;
    const float* A = bufptr(a_id);

    auto stage = [&](int kt, int b) {
        // A: 128 rows x 32 cols -> 1024 float4, 2 per thread
        const float* asrc = A + (long)m0 * 256 + kt * 32;
        float* adst = As + b * A_TILE;
#pragma unroll
        for (int j = 0; j < 2; j++) {
            int cc = j * 512 + tid;          // 0..1023
            int row = cc >> 3, c4 = cc & 7;
            cpa16(adst + row * A_STRIDE + c4 * 4, asrc + (long)row * 256 + c4 * 4);
        }
        // B: contiguous 8192 floats = 2048 float4, 4 per thread
        const float* bsrc = Wp + kt * B_TILE;
        float* bdst = Bs + b * B_TILE;
#pragma unroll
        for (int j = 0; j < 4; j++) {
            int idx = j * 512 + tid;
            cpa16(bdst + idx * 4, bsrc + idx * 4);
        }
        CP_COMMIT();
    };

    float c[2][8][4];
#pragma unroll
    for (int i = 0; i < 2; i++)
#pragma unroll
        for (int j = 0; j < 8; j++)
#pragma unroll
            for (int k2 = 0; k2 < 4; k2++) c[i][j][k2] = 0.f;

    stage(0, 0);

    for (int kt = 0; kt < 8; kt++) {
        if (kt < 7) stage(kt + 1, (kt + 1) & 1);
        if (kt < 7) { CP_WAIT(1); } else { CP_WAIT(0); }
        __syncthreads();

        const float* Ab = As + (kt & 1) * A_TILE;
        const float* Bb = Bs + (kt & 1) * B_TILE;
#pragma unroll
        for (int ks = 0; ks < 4; ks++) {
            uint32_t a[2][4];
#pragma unroll
            for (int im = 0; im < 2; im++) {
                const float* ap = Ab + (wm * 32 + im * 16 + (lane >> 2)) * A_STRIDE
                                     + ks * 8 + (lane & 3);
                a[im][0] = __float_as_uint(ap[0]);
                a[im][1] = __float_as_uint(ap[8 * A_STRIDE]);
                a[im][2] = __float_as_uint(ap[4]);
                a[im][3] = __float_as_uint(ap[8 * A_STRIDE + 4]);
            }
#pragma unroll
            for (int in = 0; in < 8; in++) {
                const float2 bv = *(const float2*)&Bb[((ks * 32 + wn * 8 + in) * 32 + lane) * 2];
                uint32_t b[2] = { __float_as_uint(bv.x), __float_as_uint(bv.y) };
#pragma unroll
                for (int im = 0; im < 2; im++) mma8(c[im][in], a[im], b);
            }
        }
        __syncthreads();
    }

    // ---- epilogue
    const float* R = rmode ? bufptr(r_id) : nullptr;
    float* O = (o_id >= 0) ? bufptr(o_id) : Oext;
#pragma unroll
    for (int im = 0; im < 2; im++) {
#pragma unroll
        for (int h = 0; h < 2; h++) {
            int row = m0 + wm * 32 + im * 16 + (lane >> 2) + h * 8;
            long ob;
            if (trans) {
                int bt = row / Nn;
                int nidx = row - bt * Nn;
                int t = bt % Tt, bbi = bt / Tt;
                ob = ((long)(bbi * Nn + nidx) * Tt + t) * 256;
            } else {
                ob = (long)row * 256;
            }
#pragma unroll
            for (int in = 0; in < 8; in++) {
                int col = wn * 64 + in * 8 + (lane & 3) * 2;
                float v0 = c[im][in][h * 2 + 0] + bias[col];
                float v1 = c[im][in][h * 2 + 1] + bias[col + 1];
                if (rmode) {
                    v0 += R[(long)row * 256 + col];
                    v1 += R[(long)row * 256 + col + 1];
                }
                if (relu) { v0 = fmaxf(v0, 0.f); v1 = fmaxf(v1, 0.f); }
                if (docvt) { v0 = tf2f(v0); v1 = tf2f(v1); }
                *(float2*)(O + ob + col) = make_float2(v0, v1);
            }
        }
    }
}

// =====================================================================
// Fused attention: per head (1 CTA, 256 threads):
//   S = q@k^T -> smem ; causal-masked softmax in smem ; O = P@V -> bufY
// S kept in smem (stride 100) -> zero DRAM traffic for scores/probs.
// =====================================================================
constexpr int S_STRIDE = 100;
constexpr int ATTN_SMEM = (96 * S_STRIDE + 6144) * 4;  // S + staging = 62976 B

__global__ __launch_bounds__(256) void attn_fused() {
    extern __shared__ float sm[];
    float* S = sm;                       // 96 x 100
    float* stage = sm + 96 * S_STRIDE;   // 6144 floats: scores As+Bs | V tiles
    float* As = stage;                   // 3072 floats
    float* Bs = stage + 3072;            // 3072 floats
    float* Vs = stage;                   // 6144 floats (PV phase)

    const int head = blockIdx.x;
    const int tid = threadIdx.x, lane = tid & 31, wid = tid >> 5;
    const int wm = wid & 1, wn = wid >> 1;   // 2 x 4 warps
    const float* qh = g_bufA + (long)head * (Tt * 256);
    const float* kh = g_bufB + (long)head * (Tt * 256);
    const float* vh = g_bufC + (long)head * (Tt * 256);

    // ---------------- phase 1: scores ----------------
    {
        float c[3][3][4] = {};
        for (int kt = 0; kt < 256; kt += 32) {
#pragma unroll
            for (int j = 0; j < 3; j++) {
                int idx = j * 256 + tid;
                int ar = idx >> 3, ac4 = idx & 7;
                float4 v = *(const float4*)(qh + ar * 256 + kt + ac4 * 4);
                int mi = ar >> 4, r = ar & 15;
                int kii = ac4 >> 1, regb = (r >> 3) + ((ac4 & 1) << 1);
                float* dst = &As[((mi * 4 + kii) * 32 + (r & 7) * 4) * 4 + regb];
                dst[0] = v.x; dst[4] = v.y; dst[8] = v.z; dst[12] = v.w;
            }
#pragma unroll
            for (int j = 0; j < 3; j++) {
                int idx = j * 256 + tid;
                int br = idx >> 3, bc4 = idx & 7;
                float4 v = *(const float4*)(kh + br * 256 + kt + bc4 * 4);
                int ni = br >> 3, nr = br & 7;
                int kii = bc4 >> 1, regb = bc4 & 1;
                float* dst = &Bs[((ni * 4 + kii) * 32 + nr * 4) * 2 + regb];
                dst[0] = v.x; dst[2] = v.y; dst[4] = v.z; dst[6] = v.w;
            }
            __syncthreads();
#pragma unroll
            for (int ks = 0; ks < 4; ks++) {
                uint32_t a[3][4], b[3][2];
#pragma unroll
                for (int im = 0; im < 3; im++) {
                    float4 av = *(const float4*)&As[(((wm * 3 + im) * 4 + ks) * 32 + lane) * 4];
                    a[im][0] = __float_as_uint(av.x); a[im][1] = __float_as_uint(av.y);
                    a[im][2] = __float_as_uint(av.z); a[im][3] = __float_as_uint(av.w);
                }
#pragma unroll
                for (int in = 0; in < 3; in++) {
                    float2 bv = *(const float2*)&Bs[(((wn * 3 + in) * 4 + ks) * 32 + lane) * 2];
                    b[in][0] = __float_as_uint(bv.x); b[in][1] = __float_as_uint(bv.y);
                }
#pragma unroll
                for (int im = 0; im < 3; im++)
#pragma unroll
                    for (int in = 0; in < 3; in++)
                        mma8(c[im][in], a[im], b[in]);
            }
            __syncthreads();
        }
        // write S tile to smem
#pragma unroll
        for (int im = 0; im < 3; im++)
#pragma unroll
            for (int h = 0; h < 2; h++) {
                int row = wm * 48 + im * 16 + (lane >> 2) + h * 8;
#pragma unroll
                for (int in = 0; in < 3; in++) {
                    int col = wn * 24 + in * 8 + (lane & 3) * 2;
                    *(float2*)(S + row * S_STRIDE + col) =
                        make_float2(c[im][in][h * 2], c[im][in][h * 2 + 1]);
                }
            }
    }
    __syncthreads();

    // ---------------- phase 2: softmax (12 rows per warp) ----------------
    {
#pragma unroll
        for (int r = 0; r < 12; r++) {
            int row = wid * 12 + r;
            float* p = S + row * S_STRIDE;
            float x[3];
#pragma unroll
            for (int j = 0; j < 3; j++) {
                int col = lane + j * 32;
                float s = p[col];
                x[j] = (col <= row) ? s * 0.0625f : (-32767.0f * 0.0625f);
            }
            float mx = fmaxf(x[0], fmaxf(x[1], x[2]));
#pragma unroll
            for (int o = 16; o > 0; o >>= 1) mx = fmaxf(mx, __shfl_xor_sync(0xffffffffu, mx, o));
            float e0 = __expf(x[0] - mx), e1 = __expf(x[1] - mx), e2 = __expf(x[2] - mx);
            float sum = e0 + e1 + e2;
#pragma unroll
            for (int o = 16; o > 0; o >>= 1) sum += __shfl_xor_sync(0xffffffffu, sum, o);
            float inv = 1.0f / sum;
            p[lane]      = tf2f(e0 * inv);
            p[lane + 32] = tf2f(e1 * inv);
            p[lane + 64] = tf2f(e2 * inv);
        }
    }
    __syncthreads();

    // ---------------- phase 3: PV (loop 4 n-tiles of 64) ----------------
    const int bbi = head / Nn, nh = head % Nn;
    for (int n0 = 0; n0 < 256; n0 += 64) {
        // pack V[0:96, n0:n0+64] into fragment layout (3 kt blocks of 32)
#pragma unroll
        for (int j = 0; j < 6; j++) {
            int idx = j * 256 + tid;           // 0..1535
            int sr = idx >> 4, f4 = idx & 15;  // s 0..95, f/4 0..15
            float4 vv = *(const float4*)(vh + sr * 256 + n0 + f4 * 4);
            int kt = sr >> 5, srl = sr & 31;
            int ni = f4 >> 1;
            int kii = srl >> 3;
            int regb = (srl >> 2) & 1;
            int lb = (f4 & 1) * 16 + (srl & 3);
            float* dst = &Vs[kt * 2048 + ((ni * 4 + kii) * 32) * 2 + regb];
            dst[(lb + 0) * 2]  = vv.x;
            dst[(lb + 4) * 2]  = vv.y;
            dst[(lb + 8) * 2]  = vv.z;
            dst[(lb + 12) * 2] = vv.w;
        }
        __syncthreads();

        float c[3][2][4] = {};
#pragma unroll
        for (int kt = 0; kt < 3; kt++) {
#pragma unroll
            for (int ks = 0; ks < 4; ks++) {
                uint32_t a[3][4], b[2][2];
#pragma unroll
                for (int im = 0; im < 3; im++) {
                    const float* ap = S + (wm * 48 + im * 16 + (lane >> 2)) * S_STRIDE
                                        + kt * 32 + ks * 8 + (lane & 3);
                    a[im][0] = __float_as_uint(ap[0]);
                    a[im][1] = __float_as_uint(ap[8 * S_STRIDE]);
                    a[im][2] = __float_as_uint(ap[4]);
                    a[im][3] = __float_as_uint(ap[8 * S_STRIDE + 4]);
                }
#pragma unroll
                for (int in = 0; in < 2; in++) {
                    float2 bv = *(const float2*)&Vs[kt * 2048 +
                        (((wn * 2 + in) * 4 + ks) * 32 + lane) * 2];
                    b[in][0] = __float_as_uint(bv.x); b[in][1] = __float_as_uint(bv.y);
                }
#pragma unroll
                for (int im = 0; im < 3; im++)
#pragma unroll
                    for (int in = 0; in < 2; in++)
                        mma8(c[im][in], a[im], b[in]);
            }
        }
#pragma unroll
        for (int im = 0; im < 3; im++)
#pragma unroll
            for (int h = 0; h < 2; h++) {
                int t = wm * 48 + im * 16 + (lane >> 2) + h * 8;
                long ob = ((long)(bbi * Tt + t) * Nn + nh) * 256;
#pragma unroll
                for (int in = 0; in < 2; in++) {
                    int f = n0 + wn * 16 + in * 8 + (lane & 3) * 2;
                    *(float2*)(g_bufY + ob + f) =
                        make_float2(tf2f(c[im][in][h * 2]), tf2f(c[im][in][h * 2 + 1]));
                }
            }
        __syncthreads();
    }
}

// =====================================================================
// LayerNorm over F=256, no affine. One warp per row. Optional tf32 output.
// =====================================================================
__global__ __launch_bounds__(256) void ln_k(int in_id, float* Oext, int out_id, int docvt) {
    const float* in = bufptr(in_id);
    float* out = (out_id >= 0) ? bufptr(out_id) : Oext;
    long row = (long)blockIdx.x * 8 + (threadIdx.x >> 5);
    int lane = threadIdx.x & 31;
    const float* p = in + row * 256;
    float4 a = *(const float4*)(p + lane * 4);
    float4 b = *(const float4*)(p + 128 + lane * 4);
    float s = a.x + a.y + a.z + a.w + b.x + b.y + b.z + b.w;
    float q = a.x * a.x + a.y * a.y + a.z * a.z + a.w * a.w +
              b.x * b.x + b.y * b.y + b.z * b.z + b.w * b.w;
#pragma unroll
    for (int o = 16; o > 0; o >>= 1) {
        s += __shfl_xor_sync(0xffffffffu, s, o);
        q += __shfl_xor_sync(0xffffffffu, q, o);
    }
    float mean = s * (1.0f / 256.0f);
    float var = q * (1.0f / 256.0f) - mean * mean;
    float rs = rsqrtf(var + 1e-5f);
    float4 oa = make_float4((a.x - mean) * rs, (a.y - mean) * rs,
                            (a.z - mean) * rs, (a.w - mean) * rs);
    float4 ob = make_float4((b.x - mean) * rs, (b.y - mean) * rs,
                            (b.z - mean) * rs, (b.w - mean) * rs);
    if (docvt) {
        oa.x = tf2f(oa.x); oa.y = tf2f(oa.y); oa.z = tf2f(oa.z); oa.w = tf2f(oa.w);
        ob.x = tf2f(ob.x); ob.y = tf2f(ob.y); ob.z = tf2f(ob.z); ob.w = tf2f(ob.w);
    }
    float* op = out + row * 256;
    *(float4*)(op + lane * 4) = oa;
    *(float4*)(op + 128 + lane * 4) = ob;
}

// =====================================================================
extern "C" void kernel_launch(void* const* d_in, const int* in_sizes, int n_in,
                              void* d_out, int out_size) {
    const float* xl  = (const float*)d_in[0];
    const float* xh  = (const float*)d_in[1];
    const float* te  = (const float*)d_in[2];
    const float* Wq  = (const float*)d_in[3];
    const float* bq  = (const float*)d_in[4];
    const float* Wk  = (const float*)d_in[5];
    const float* bk  = (const float*)d_in[6];
    const float* Wv  = (const float*)d_in[7];
    const float* bv  = (const float*)d_in[8];
    const float* Wo  = (const float*)d_in[9];
    const float* bo  = (const float*)d_in[10];
    const float* Wf1 = (const float*)d_in[11];
    const float* bf1 = (const float*)d_in[12];
    const float* Wf2 = (const float*)d_in[13];
    const float* bf2 = (const float*)d_in[14];
    float* out = (float*)d_out;

    static bool init = false;
    static float* wbase = nullptr;
    if (!init) {
        cudaFuncSetAttribute(gemm_f, cudaFuncAttributeMaxDynamicSharedMemorySize, GEMM_SMEM);
        cudaFuncSetAttribute(attn_fused, cudaFuncAttributeMaxDynamicSharedMemorySize, ATTN_SMEM);
        cudaGetSymbolAddress((void**)&wbase, g_bufW);
        init = true;
    }

    prep_x<<<Mtot / 4, 256>>>(xl, xh, te);
    pack_w6<<<1536, 256>>>(Wq, Wk, Wv, Wo, Wf1, Wf2);

    dim3 gg(Mtot / 128);   // 2400 CTAs per dense GEMM

    // q = X @ Wq^T + bq                    -> bufA [B,N,T,F] (tf32)
    gemm_f<<<gg, 512, GEMM_SMEM>>>(5, wbase + 0 * 65536, bq, -1, nullptr, 0, 0, 1, 0, 1);
    // k = relu(H @ Wk^T + bk)              -> bufB [B,N,T,F] (tf32)
    gemm_f<<<gg, 512, GEMM_SMEM>>>(6, wbase + 1 * 65536, bk, -1, nullptr, 1, 1, 1, 0, 1);
    // v = relu(H @ Wv^T + bv)              -> bufC [B,N,T,F] (tf32)
    gemm_f<<<gg, 512, GEMM_SMEM>>>(6, wbase + 2 * 65536, bv, -1, nullptr, 2, 1, 1, 0, 1);

    attn_fused<<<HEADS, 256, ATTN_SMEM>>>();       // -> bufY (tf32)

    // attn_proj + residual X               -> bufC
    gemm_f<<<gg, 512, GEMM_SMEM>>>(3, wbase + 3 * 65536, bo, 5, nullptr, 2, 0, 0, 1, 0);
    ln_k<<<Mtot / 8, 256>>>(2, nullptr, 2, 1);     // out1 = LN(...), tf32

    // h = relu(out1 @ Wf1^T + bf1)         -> bufA (tf32)
    gemm_f<<<gg, 512, GEMM_SMEM>>>(2, wbase + 4 * 65536, bf1, -1, nullptr, 0, 1, 0, 0, 1);
    // h2 = h @ Wf2^T + bf2 + out1          -> bufB
    gemm_f<<<gg, 512, GEMM_SMEM>>>(0, wbase + 5 * 65536, bf2, 2, nullptr, 1, 0, 0, 1, 0);
    ln_k<<<Mtot / 8, 256>>>(1, out, -1, 0);        // final LN -> d_out (fp32)
}

// round 8
// speedup vs baseline: 1.0686x; 1.0686x over previous
#include <cuda_runtime.h>
#include <cstdint>

#define DINL __device__ __forceinline__

constexpr int Tt = 96, Nn = 400, Fd = 256;
constexpr int Bb = 8;
constexpr int Mtot = Bb * Tt * Nn;              // 307200
constexpr int HEADS = Bb * Nn;                  // 3200
constexpr long BUF_ELEMS = (long)Mtot * Fd;     // 78,643,200

// ---------------- scratch (device globals; no allocation APIs) ----------------
__device__ float g_bufA[BUF_ELEMS];                 // q  -> ff1 out
__device__ float g_bufB[BUF_ELEMS];                 // k  -> ff2 out (pre-LN)
__device__ float g_bufC[BUF_ELEMS];                 // v  -> attn-proj out / out1
__device__ float g_bufY[BUF_ELEMS];                 // attention output [B,T,N,F]
__device__ float g_bufX[BUF_ELEMS];                 // tf32(xl + te)
__device__ float g_bufH[BUF_ELEMS];                 // tf32(xh + te)
__device__ float g_bufW[6 * 256 * 256];             // pre-packed tf32 weight fragments

DINL float* bufptr(int id) {
    switch (id) {
        case 0: return g_bufA;
        case 1: return g_bufB;
        case 2: return g_bufC;
        case 3: return g_bufY;
        case 5: return g_bufX;
        default: return g_bufH;
    }
}

// ---------------- tf32 + async-copy helpers ----------------
DINL uint32_t f2tf(float x) {
    uint32_t r;
    asm("cvt.rna.tf32.f32 %0, %1;" : "=r"(r) : "f"(x));
    return r;
}
DINL float tf2f(float x) { return __uint_as_float(f2tf(x)); }

DINL void mma8(float* c, const uint32_t* a, const uint32_t* b) {
    asm volatile(
        "mma.sync.aligned.m16n8k8.row.col.f32.tf32.tf32.f32 "
        "{%0,%1,%2,%3}, {%4,%5,%6,%7}, {%8,%9}, {%0,%1,%2,%3};"
        : "+f"(c[0]), "+f"(c[1]), "+f"(c[2]), "+f"(c[3])
        : "r"(a[0]), "r"(a[1]), "r"(a[2]), "r"(a[3]), "r"(b[0]), "r"(b[1]));
}

DINL void cpa16(float* smem_dst, const float* gsrc) {
    uint32_t d = (uint32_t)__cvta_generic_to_shared(smem_dst);
    asm volatile("cp.async.cg.shared.global [%0], [%1], 16;\n" :: "r"(d), "l"(gsrc));
}
#define CP_COMMIT()  asm volatile("cp.async.commit_group;\n")
#define CP_WAIT(n)   asm volatile("cp.async.wait_group %0;\n" :: "n"(n))

// =====================================================================
// Pre-pass: X = tf32(xl + te), H = tf32(xh + te)
// =====================================================================
__global__ __launch_bounds__(256) void prep_x(
    const float* __restrict__ xl, const float* __restrict__ xh,
    const float* __restrict__ te)
{
    long i = (long)blockIdx.x * 256 + threadIdx.x;   // float4 index
    long e = i * 4;
    int m = (int)(e >> 8);
    int bt = m / Nn;
    int f = (int)(e & 255);
    float4 t4 = *(const float4*)(te + bt * 256 + f);
    float4 a = *(const float4*)(xl + e);
    float4 b = *(const float4*)(xh + e);
    a.x = tf2f(a.x + t4.x); a.y = tf2f(a.y + t4.y);
    a.z = tf2f(a.z + t4.z); a.w = tf2f(a.w + t4.w);
    b.x = tf2f(b.x + t4.x); b.y = tf2f(b.y + t4.y);
    b.z = tf2f(b.z + t4.z); b.w = tf2f(b.w + t4.w);
    *(float4*)(g_bufX + e) = a;
    *(float4*)(g_bufH + e) = b;
}

// =====================================================================
// Pack all 6 weights [256x256] (W[n][k]) into fragment layout:
//   g_bufW[widx*65536 + ((kb*32 + nb)*32 + lane)*2 + reg]
//   kb = k>>3, nb = n>>3, lane = (n&7)*4 + (k&3), reg = (k>>2)&1
// =====================================================================
__global__ __launch_bounds__(256) void pack_w6(
    const float* __restrict__ W0, const float* __restrict__ W1,
    const float* __restrict__ W2, const float* __restrict__ W3,
    const float* __restrict__ W4, const float* __restrict__ W5)
{
    int widx = blockIdx.x >> 8;
    const float* W;
    switch (widx) {
        case 0: W = W0; break;
        case 1: W = W1; break;
        case 2: W = W2; break;
        case 3: W = W3; break;
        case 4: W = W4; break;
        default: W = W5; break;
    }
    int i = (blockIdx.x & 255) * 256 + threadIdx.x;  // 0..65535
    int n = i >> 8, k = i & 255;
    int kb = k >> 3, nb = n >> 3;
    int lanei = (n & 7) * 4 + (k & 3);
    int reg = (k >> 2) & 1;
    g_bufW[widx * 65536 + ((kb * 32 + nb) * 32 + lanei) * 2 + reg] = tf2f(W[i]);
}

// =====================================================================
// Dense GEMM v5: out[m,n] = act( A[m,:] @ W[n,:] + bias[n] (+R) )
// M=307200, N=256, K=256. BM=64, BN=128 (grid.y = n-half), BK=32.
// 256 threads (2m x 4n warps, warp tile 32x32). 3 CTAs/SM target.
// =====================================================================
constexpr int A_STRIDE = 36;                     // 32 + 4 pad
constexpr int A_TILE = 64 * A_STRIDE;            // 2304 floats per buffer
constexpr int B_TILE = 4096;                     // 32k x 128n packed slice
constexpr int GEMM_SMEM = (2 * B_TILE + 2 * A_TILE) * 4;   // 51200 bytes

__global__ __launch_bounds__(256, 3) void gemm_f(
    int a_id, const float* __restrict__ Wp, const float* __restrict__ bias,
    int r_id, float* __restrict__ Oext, int o_id,
    int relu, int trans, int rmode, int docvt)
{
    extern __shared__ float sm[];
    float* Bs = sm;                      // 2 x 4096
    float* As = sm + 2 * B_TILE;         // 2 x 2304

    const int tid = threadIdx.x;
    const int lane = tid & 31, wid = tid >> 5;
    const int wm = wid & 1, wn = wid >> 2;       // careful: want 2m x 4n
    const int wnn = (wid >> 1) & 3;              // 4 n-warps
    const int wmm = wid & 1;
    const int m0 = blockIdx.x * 64;
    const int nhalf = blockIdx.y;                // 0 or 1
    const int nb_off = nhalf * 1024;             // 16 nb-blocks * 64 floats
    const float* A = bufptr(a_id);
    (void)wm; (void)wn;

    auto stage = [&](int kt, int b) {
        // A: 64 rows x 32 cols -> 512 float4, 2 per thread
        const float* asrc = A + (long)m0 * 256 + kt * 32;
        float* adst = As + b * A_TILE;
#pragma unroll
        for (int j = 0; j < 2; j++) {
            int cc = j * 256 + tid;          // 0..511
            int row = cc >> 3, c4 = cc & 7;
            cpa16(adst + row * A_STRIDE + c4 * 4, asrc + (long)row * 256 + c4 * 4);
        }
        // B: 4 kb-chunks of 1024 floats (stride 2048 in source)
        const float* bsrc = Wp + kt * 8192 + nb_off;
        float* bdst = Bs + b * B_TILE;
#pragma unroll
        for (int j = 0; j < 4; j++) {
            int c = j * 256 + tid;           // float4 index 0..1023
            int chunk = c >> 8, within = c & 255;
            cpa16(bdst + chunk * 1024 + within * 4, bsrc + chunk * 2048 + within * 4);
        }
        CP_COMMIT();
    };

    float c[2][4][4];
#pragma unroll
    for (int i = 0; i < 2; i++)
#pragma unroll
        for (int j = 0; j < 4; j++)
#pragma unroll
            for (int k2 = 0; k2 < 4; k2++) c[i][j][k2] = 0.f;

    stage(0, 0);

    for (int kt = 0; kt < 8; kt++) {
        if (kt < 7) stage(kt + 1, (kt + 1) & 1);
        if (kt < 7) { CP_WAIT(1); } else { CP_WAIT(0); }
        __syncthreads();

        const float* Ab = As + (kt & 1) * A_TILE;
        const float* Bb = Bs + (kt & 1) * B_TILE;
#pragma unroll
        for (int ks = 0; ks < 4; ks++) {
            uint32_t a[2][4];
#pragma unroll
            for (int im = 0; im < 2; im++) {
                const float* ap = Ab + (wmm * 32 + im * 16 + (lane >> 2)) * A_STRIDE
                                     + ks * 8 + (lane & 3);
                a[im][0] = __float_as_uint(ap[0]);
                a[im][1] = __float_as_uint(ap[8 * A_STRIDE]);
                a[im][2] = __float_as_uint(ap[4]);
                a[im][3] = __float_as_uint(ap[8 * A_STRIDE + 4]);
            }
#pragma unroll
            for (int in = 0; in < 4; in++) {
                const float2 bv = *(const float2*)&Bb[ks * 1024 + (wnn * 4 + in) * 64 + lane * 2];
                uint32_t b[2] = { __float_as_uint(bv.x), __float_as_uint(bv.y) };
#pragma unroll
                for (int im = 0; im < 2; im++) mma8(c[im][in], a[im], b);
            }
        }
        __syncthreads();
    }

    // ---- epilogue
    const float* R = rmode ? bufptr(r_id) : nullptr;
    float* O = (o_id >= 0) ? bufptr(o_id) : Oext;
#pragma unroll
    for (int im = 0; im < 2; im++) {
#pragma unroll
        for (int h = 0; h < 2; h++) {
            int row = m0 + wmm * 32 + im * 16 + (lane >> 2) + h * 8;
            long ob;
            if (trans) {
                int bt = row / Nn;
                int nidx = row - bt * Nn;
                int t = bt % Tt, bbi = bt / Tt;
                ob = ((long)(bbi * Nn + nidx) * Tt + t) * 256;
            } else {
                ob = (long)row * 256;
            }
#pragma unroll
            for (int in = 0; in < 4; in++) {
                int col = nhalf * 128 + wnn * 32 + in * 8 + (lane & 3) * 2;
                float v0 = c[im][in][h * 2 + 0] + bias[col];
                float v1 = c[im][in][h * 2 + 1] + bias[col + 1];
                if (rmode) {
                    v0 += R[(long)row * 256 + col];
                    v1 += R[(long)row * 256 + col + 1];
                }
                if (relu) { v0 = fmaxf(v0, 0.f); v1 = fmaxf(v1, 0.f); }
                if (docvt) { v0 = tf2f(v0); v1 = tf2f(v1); }
                *(float2*)(O + ob + col) = make_float2(v0, v1);
            }
        }
    }
}

// =====================================================================
// Fused attention: per head (1 CTA, 256 threads):
//   S = q@k^T -> smem ; causal-masked softmax in smem ; O = P@V -> bufY
// =====================================================================
constexpr int S_STRIDE = 100;
constexpr int ATTN_SMEM = (96 * S_STRIDE + 6144) * 4;  // 62976 B

__global__ __launch_bounds__(256) void attn_fused() {
    extern __shared__ float sm[];
    float* S = sm;                       // 96 x 100
    float* As = sm + 96 * S_STRIDE;      // 3072
    float* Bs = As + 3072;               // 3072
    float* Vs = As;                      // 6144 (PV phase)

    const int head = blockIdx.x;
    const int tid = threadIdx.x, lane = tid & 31, wid = tid >> 5;
    const int wm = wid & 1, wn = wid >> 1;   // 2 x 4 warps
    const float* qh = g_bufA + (long)head * (Tt * 256);
    const float* kh = g_bufB + (long)head * (Tt * 256);
    const float* vh = g_bufC + (long)head * (Tt * 256);

    // ---------------- phase 1: scores ----------------
    {
        float c[3][3][4] = {};
        for (int kt = 0; kt < 256; kt += 32) {
#pragma unroll
            for (int j = 0; j < 3; j++) {
                int idx = j * 256 + tid;
                int ar = idx >> 3, ac4 = idx & 7;
                float4 v = *(const float4*)(qh + ar * 256 + kt + ac4 * 4);
                int mi = ar >> 4, r = ar & 15;
                int kii = ac4 >> 1, regb = (r >> 3) + ((ac4 & 1) << 1);
                float* dst = &As[((mi * 4 + kii) * 32 + (r & 7) * 4) * 4 + regb];
                dst[0] = v.x; dst[4] = v.y; dst[8] = v.z; dst[12] = v.w;
            }
#pragma unroll
            for (int j = 0; j < 3; j++) {
                int idx = j * 256 + tid;
                int br = idx >> 3, bc4 = idx & 7;
                float4 v = *(const float4*)(kh + br * 256 + kt + bc4 * 4);
                int ni = br >> 3, nr = br & 7;
                int kii = bc4 >> 1, regb = bc4 & 1;
                float* dst = &Bs[((ni * 4 + kii) * 32 + nr * 4) * 2 + regb];
                dst[0] = v.x; dst[2] = v.y; dst[4] = v.z; dst[6] = v.w;
            }
            __syncthreads();
#pragma unroll
            for (int ks = 0; ks < 4; ks++) {
                uint32_t a[3][4], b[3][2];
#pragma unroll
                for (int im = 0; im < 3; im++) {
                    float4 av = *(const float4*)&As[(((wm * 3 + im) * 4 + ks) * 32 + lane) * 4];
                    a[im][0] = __float_as_uint(av.x); a[im][1] = __float_as_uint(av.y);
                    a[im][2] = __float_as_uint(av.z); a[im][3] = __float_as_uint(av.w);
                }
#pragma unroll
                for (int in = 0; in < 3; in++) {
                    float2 bv = *(const float2*)&Bs[(((wn * 3 + in) * 4 + ks) * 32 + lane) * 2];
                    b[in][0] = __float_as_uint(bv.x); b[in][1] = __float_as_uint(bv.y);
                }
#pragma unroll
                for (int im = 0; im < 3; im++)
#pragma unroll
                    for (int in = 0; in < 3; in++)
                        mma8(c[im][in], a[im], b[in]);
            }
            __syncthreads();
        }
#pragma unroll
        for (int im = 0; im < 3; im++)
#pragma unroll
            for (int h = 0; h < 2; h++) {
                int row = wm * 48 + im * 16 + (lane >> 2) + h * 8;
#pragma unroll
                for (int in = 0; in < 3; in++) {
                    int col = wn * 24 + in * 8 + (lane & 3) * 2;
                    *(float2*)(S + row * S_STRIDE + col) =
                        make_float2(c[im][in][h * 2], c[im][in][h * 2 + 1]);
                }
            }
    }
    __syncthreads();

    // ---------------- phase 2: softmax ----------------
#pragma unroll
    for (int r = 0; r < 12; r++) {
        int row = wid * 12 + r;
        float* p = S + row * S_STRIDE;
        float x[3];
#pragma unroll
        for (int j = 0; j < 3; j++) {
            int col = lane + j * 32;
            float s = p[col];
            x[j] = (col <= row) ? s * 0.0625f : (-32767.0f * 0.0625f);
        }
        float mx = fmaxf(x[0], fmaxf(x[1], x[2]));
#pragma unroll
        for (int o = 16; o > 0; o >>= 1) mx = fmaxf(mx, __shfl_xor_sync(0xffffffffu, mx, o));
        float e0 = __expf(x[0] - mx), e1 = __expf(x[1] - mx), e2 = __expf(x[2] - mx);
        float sum = e0 + e1 + e2;
#pragma unroll
        for (int o = 16; o > 0; o >>= 1) sum += __shfl_xor_sync(0xffffffffu, sum, o);
        float inv = 1.0f / sum;
        p[lane]      = tf2f(e0 * inv);
        p[lane + 32] = tf2f(e1 * inv);
        p[lane + 64] = tf2f(e2 * inv);
    }
    __syncthreads();

    // ---------------- phase 3: PV ----------------
    const int bbi = head / Nn, nh = head % Nn;
    for (int n0 = 0; n0 < 256; n0 += 64) {
#pragma unroll
        for (int j = 0; j < 6; j++) {
            int idx = j * 256 + tid;
            int sr = idx >> 4, f4 = idx & 15;
            float4 vv = *(const float4*)(vh + sr * 256 + n0 + f4 * 4);
            int kt = sr >> 5, srl = sr & 31;
            int ni = f4 >> 1;
            int kii = srl >> 3;
            int regb = (srl >> 2) & 1;
            int lb = (f4 & 1) * 16 + (srl & 3);
            float* dst = &Vs[kt * 2048 + ((ni * 4 + kii) * 32) * 2 + regb];
            dst[(lb + 0) * 2]  = vv.x;
            dst[(lb + 4) * 2]  = vv.y;
            dst[(lb + 8) * 2]  = vv.z;
            dst[(lb + 12) * 2] = vv.w;
        }
        __syncthreads();

        float c[3][2][4] = {};
#pragma unroll
        for (int kt = 0; kt < 3; kt++) {
#pragma unroll
            for (int ks = 0; ks < 4; ks++) {
                uint32_t a[3][4], b[2][2];
#pragma unroll
                for (int im = 0; im < 3; im++) {
                    const float* ap = S + (wm * 48 + im * 16 + (lane >> 2)) * S_STRIDE
                                        + kt * 32 + ks * 8 + (lane & 3);
                    a[im][0] = __float_as_uint(ap[0]);
                    a[im][1] = __float_as_uint(ap[8 * S_STRIDE]);
                    a[im][2] = __float_as_uint(ap[4]);
                    a[im][3] = __float_as_uint(ap[8 * S_STRIDE + 4]);
                }
#pragma unroll
                for (int in = 0; in < 2; in++) {
                    float2 bv = *(const float2*)&Vs[kt * 2048 +
                        (((wn * 2 + in) * 4 + ks) * 32 + lane) * 2];
                    b[in][0] = __float_as_uint(bv.x); b[in][1] = __float_as_uint(bv.y);
                }
#pragma unroll
                for (int im = 0; im < 3; im++)
#pragma unroll
                    for (int in = 0; in < 2; in++)
                        mma8(c[im][in], a[im], b[in]);
            }
        }
#pragma unroll
        for (int im = 0; im < 3; im++)
#pragma unroll
            for (int h = 0; h < 2; h++) {
                int t = wm * 48 + im * 16 + (lane >> 2) + h * 8;
                long ob = ((long)(bbi * Tt + t) * Nn + nh) * 256;
#pragma unroll
                for (int in = 0; in < 2; in++) {
                    int f = n0 + wn * 16 + in * 8 + (lane & 3) * 2;
                    *(float2*)(g_bufY + ob + f) =
                        make_float2(tf2f(c[im][in][h * 2]), tf2f(c[im][in][h * 2 + 1]));
                }
            }
        __syncthreads();
    }
}

// =====================================================================
// LayerNorm over F=256, no affine. One warp per row. Optional tf32 output.
// =====================================================================
__global__ __launch_bounds__(256) void ln_k(int in_id, float* Oext, int out_id, int docvt) {
    const float* in = bufptr(in_id);
    float* out = (out_id >= 0) ? bufptr(out_id) : Oext;
    long row = (long)blockIdx.x * 8 + (threadIdx.x >> 5);
    int lane = threadIdx.x & 31;
    const float* p = in + row * 256;
    float4 a = *(const float4*)(p + lane * 4);
    float4 b = *(const float4*)(p + 128 + lane * 4);
    float s = a.x + a.y + a.z + a.w + b.x + b.y + b.z + b.w;
    float q = a.x * a.x + a.y * a.y + a.z * a.z + a.w * a.w +
              b.x * b.x + b.y * b.y + b.z * b.z + b.w * b.w;
#pragma unroll
    for (int o = 16; o > 0; o >>= 1) {
        s += __shfl_xor_sync(0xffffffffu, s, o);
        q += __shfl_xor_sync(0xffffffffu, q, o);
    }
    float mean = s * (1.0f / 256.0f);
    float var = q * (1.0f / 256.0f) - mean * mean;
    float rs = rsqrtf(var + 1e-5f);
    float4 oa = make_float4((a.x - mean) * rs, (a.y - mean) * rs,
                            (a.z - mean) * rs, (a.w - mean) * rs);
    float4 ob = make_float4((b.x - mean) * rs, (b.y - mean) * rs,
                            (b.z - mean) * rs, (b.w - mean) * rs);
    if (docvt) {
        oa.x = tf2f(oa.x); oa.y = tf2f(oa.y); oa.z = tf2f(oa.z); oa.w = tf2f(oa.w);
        ob.x = tf2f(ob.x); ob.y = tf2f(ob.y); ob.z = tf2f(ob.z); ob.w = tf2f(ob.w);
    }
    float* op = out + row * 256;
    *(float4*)(op + lane * 4) = oa;
    *(float4*)(op + 128 + lane * 4) = ob;
}

// =====================================================================
extern "C" void kernel_launch(void* const* d_in, const int* in_sizes, int n_in,
                              void* d_out, int out_size) {
    const float* xl  = (const float*)d_in[0];
    const float* xh  = (const float*)d_in[1];
    const float* te  = (const float*)d_in[2];
    const float* Wq  = (const float*)d_in[3];
    const float* bq  = (const float*)d_in[4];
    const float* Wk  = (const float*)d_in[5];
    const float* bk  = (const float*)d_in[6];
    const float* Wv  = (const float*)d_in[7];
    const float* bv  = (const float*)d_in[8];
    const float* Wo  = (const float*)d_in[9];
    const float* bo  = (const float*)d_in[10];
    const float* Wf1 = (const float*)d_in[11];
    const float* bf1 = (const float*)d_in[12];
    const float* Wf2 = (const float*)d_in[13];
    const float* bf2 = (const float*)d_in[14];
    float* out = (float*)d_out;

    static bool init = false;
    static float* wbase = nullptr;
    if (!init) {
        cudaFuncSetAttribute(gemm_f, cudaFuncAttributeMaxDynamicSharedMemorySize, GEMM_SMEM);
        cudaFuncSetAttribute(attn_fused, cudaFuncAttributeMaxDynamicSharedMemorySize, ATTN_SMEM);
        cudaGetSymbolAddress((void**)&wbase, g_bufW);
        init = true;
    }

    prep_x<<<Mtot / 4, 256>>>(xl, xh, te);
    pack_w6<<<1536, 256>>>(Wq, Wk, Wv, Wo, Wf1, Wf2);

    dim3 gg(Mtot / 64, 2);   // 4800 x 2 CTAs per dense GEMM

    // q = X @ Wq^T + bq                    -> bufA [B,N,T,F] (tf32)
    gemm_f<<<gg, 256, GEMM_SMEM>>>(5, wbase + 0 * 65536, bq, -1, nullptr, 0, 0, 1, 0, 1);
    // k = relu(H @ Wk^T + bk)              -> bufB [B,N,T,F] (tf32)
    gemm_f<<<gg, 256, GEMM_SMEM>>>(6, wbase + 1 * 65536, bk, -1, nullptr, 1, 1, 1, 0, 1);
    // v = relu(H @ Wv^T + bv)              -> bufC [B,N,T,F] (tf32)
    gemm_f<<<gg, 256, GEMM_SMEM>>>(6, wbase + 2 * 65536, bv, -1, nullptr, 2, 1, 1, 0, 1);

    attn_fused<<<HEADS, 256, ATTN_SMEM>>>();       // -> bufY (tf32)

    // attn_proj + residual X               -> bufC
    gemm_f<<<gg, 256, GEMM_SMEM>>>(3, wbase + 3 * 65536, bo, 5, nullptr, 2, 0, 0, 1, 0);
    ln_k<<<Mtot / 8, 256>>>(2, nullptr, 2, 1);     // out1 = LN(...), tf32

    // h = relu(out1 @ Wf1^T + bf1)         -> bufA (tf32)
    gemm_f<<<gg, 256, GEMM_SMEM>>>(2, wbase + 4 * 65536, bf1, -1, nullptr, 0, 1, 0, 0, 1);
    // h2 = h @ Wf2^T + bf2 + out1          -> bufB
    gemm_f<<<gg, 256, GEMM_SMEM>>>(0, wbase + 5 * 65536, bf2, 2, nullptr, 1, 0, 0, 1, 0);
    ln_k<<<Mtot / 8, 256>>>(1, out, -1, 0);        // final LN -> d_out (fp32)
}